// round 1
// baseline (speedup 1.0000x reference)
#include <cuda_runtime.h>
#include <cuda_bf16.h>

#define D       256
#define L       50
#define BM      16
#define NBLK    (4096 / BM)          // 256 blocks
#define IDXROW  (3 * L + 4)          // 154 indices per batch

// Repacked transposed weights: w?p[((j>>2)*256 + i)*4 + (j&3)] = w[i][j]
// so thread i reads float4 {w[i][4j4..4j4+3]} at a coalesced address.
__device__ float g_w1p[D * D];
__device__ float g_w2p[D * D];

__global__ void __launch_bounds__(256) repack_weights(
    const float* __restrict__ w1, const float* __restrict__ w2)
{
    int i = blockIdx.x;       // row of w (output dim)
    int j = threadIdx.x;      // col of w (k dim) — coalesced read of row i
    float v1 = w1[i * D + j];
    float v2 = w2[i * D + j];
    int o = ((j >> 2) * D + i) * 4 + (j & 3);
    g_w1p[o] = v1;
    g_w2p[o] = v2;
}

__device__ __forceinline__ float fsigmoid(float x) {
    return 1.0f / (1.0f + __expf(-x));
}

__global__ void __launch_bounds__(256) slotgate_kernel(
    const int*   __restrict__ acts_req,
    const int*   __restrict__ acts_slot,
    const int*   __restrict__ acts_val,
    const int*   __restrict__ slot_names,
    const float* __restrict__ emb,
    float*       __restrict__ out)
{
    __shared__ __align__(16) float tq_sm [BM][D];   // 16 KB
    __shared__ __align__(16) float tsv_sm[BM][D];   // 16 KB
    __shared__ int idx_sm[BM][IDXROW];              // ~9.6 KB

    const int tid = threadIdx.x;
    const int b0  = blockIdx.x * BM;

    // ---- load all indices for this block's BM batches into smem ----
    for (int k = tid; k < BM * IDXROW; k += 256) {
        int b = k / IDXROW;
        int r = k - b * IDXROW;
        int gb = b0 + b;
        int v;
        if      (r < L)      v = acts_req [gb * L + r];
        else if (r < 2 * L)  v = acts_slot[gb * L + (r - L)];
        else if (r < 3 * L)  v = acts_val [gb * L + (r - 2 * L)];
        else                 v = slot_names[gb * 4 + (r - 3 * L)];
        idx_sm[b][r] = v;
    }
    __syncthreads();

    // ---- Phase 1: gather-sum (float4 wide loads, L2-bandwidth bound) ----
    {
        const float4* __restrict__ emb4 = (const float4*)emb;
        const int team = tid >> 6;     // 4 teams of 64 threads (2 warps)
        const int lane = tid & 63;     // float4 channel index: channels 4*lane..+3
        for (int bb = 0; bb < 4; bb++) {
            const int b = team * 4 + bb;
            float4 q  = make_float4(0.f, 0.f, 0.f, 0.f);
            float4 sv = make_float4(0.f, 0.f, 0.f, 0.f);
            #pragma unroll 10
            for (int l = 0; l < L; l++) {
                float4 e = emb4[(size_t)idx_sm[b][l] * 64 + lane];
                q.x += e.x; q.y += e.y; q.z += e.z; q.w += e.w;
            }
            #pragma unroll 10
            for (int l = L; l < 3 * L; l++) {
                float4 e = emb4[(size_t)idx_sm[b][l] * 64 + lane];
                sv.x += e.x; sv.y += e.y; sv.z += e.z; sv.w += e.w;
            }
            ((float4*)tq_sm [b])[lane] = q;
            ((float4*)tsv_sm[b])[lane] = sv;
        }
    }
    __syncthreads();

    // ---- Phase 2: g_q[b][i] = sum_j w1[i][j] * t_q[b][j]  (and g_sv) ----
    const int i = tid;  // output channel owned by this thread
    float accq[BM], accs[BM];
    #pragma unroll
    for (int b = 0; b < BM; b++) { accq[b] = 0.f; accs[b] = 0.f; }

    {
        const float4* __restrict__ w1v = (const float4*)g_w1p;
        const float4* __restrict__ w2v = (const float4*)g_w2p;
        for (int j4 = 0; j4 < D / 4; j4++) {
            float4 wq = w1v[j4 * D + i];   // coalesced LDG.128
            float4 ws = w2v[j4 * D + i];
            #pragma unroll
            for (int b = 0; b < BM; b++) {
                float4 t = ((const float4*)tq_sm [b])[j4];  // broadcast LDS.128
                float4 u = ((const float4*)tsv_sm[b])[j4];
                accq[b] += wq.x * t.x + wq.y * t.y + wq.z * t.z + wq.w * t.w;
                accs[b] += ws.x * u.x + ws.y * u.y + ws.z * u.z + ws.w * u.w;
            }
        }
    }

    // ---- Epilogue: gates = c_s + sig(c_s*g_q) + sig(c_s*g_sv) ----
    for (int b = 0; b < BM; b++) {
        const float gq = accq[b];
        const float gs = accs[b];
        const size_t ob = ((size_t)(b0 + b)) * 4;
        #pragma unroll
        for (int s = 0; s < 4; s++) {
            int row = idx_sm[b][3 * L + s];
            float c = emb[(size_t)row * D + i];        // coalesced
            float o = c + fsigmoid(c * gq) + fsigmoid(c * gs);
            out[(ob + s) * D + i] = o;                 // coalesced
        }
    }
}

extern "C" void kernel_launch(void* const* d_in, const int* in_sizes, int n_in,
                              void* d_out, int out_size)
{
    const int*   acts_req   = (const int*)  d_in[0];
    const int*   acts_slot  = (const int*)  d_in[1];
    const int*   acts_val   = (const int*)  d_in[2];
    const int*   slot_names = (const int*)  d_in[3];
    const float* emb        = (const float*)d_in[4];
    const float* w1         = (const float*)d_in[5];
    const float* w2         = (const float*)d_in[6];
    float*       out        = (float*)d_out;

    repack_weights<<<D, D>>>(w1, w2);
    slotgate_kernel<<<NBLK, 256>>>(acts_req, acts_slot, acts_val,
                                   slot_names, emb, out);
}

// round 2
// speedup vs baseline: 1.5266x; 1.5266x over previous
#include <cuda_runtime.h>

#define D       256
#define L       50
#define BSZ     4096
#define BM2     16
#define NBLK2   (BSZ / BM2)

// Repacked transposed weights: float4 at [j4*D + i] = {w[i][4j4..4j4+3]}
__device__ float g_w1p[D * D];
__device__ float g_w2p[D * D];
// Scratch: t_q / t_sv per batch, as 64 float4 channels per batch (8 MB total)
__device__ float4 g_tq [BSZ * (D / 4)];
__device__ float4 g_tsv[BSZ * (D / 4)];

#define PACK2(u, x, y)   asm("mov.b64 %0, {%1, %2};" : "=l"(u) : "f"(x), "f"(y))
#define UNPACK2(x, y, u) asm("mov.b64 {%0, %1}, %2;" : "=f"(x), "=f"(y) : "l"(u))
#define FMA2(acc, a, b)  asm("fma.rn.f32x2 %0, %1, %2, %0;" : "+l"(acc) : "l"(a), "l"(b))

__global__ void __launch_bounds__(256) repack_weights(
    const float* __restrict__ w1, const float* __restrict__ w2)
{
    int i = blockIdx.x;       // row of w (output dim)
    int j = threadIdx.x;      // col of w (k dim) — coalesced read of row i
    float v1 = w1[i * D + j];
    float v2 = w2[i * D + j];
    int o = ((j >> 2) * D + i) * 4 + (j & 3);
    g_w1p[o] = v1;
    g_w2p[o] = v2;
}

// ---------------- Kernel 1: ragged gather-sum, one block per batch ----------
__global__ void __launch_bounds__(256) gather_kernel(
    const int*   __restrict__ acts_req,
    const int*   __restrict__ acts_slot,
    const int*   __restrict__ acts_val,
    const float* __restrict__ emb)
{
    __shared__ int idx[3 * L + 2];
    __shared__ __align__(16) float4 redq [4][D / 4];   // 4 KB
    __shared__ __align__(16) float4 redsv[4][D / 4];   // 4 KB

    const int b   = blockIdx.x;
    const int tid = threadIdx.x;

    if (tid < 3 * L) {
        int v;
        if      (tid < L)     v = acts_req [b * L + tid];
        else if (tid < 2 * L) v = acts_slot[b * L + (tid - L)];
        else                  v = acts_val [b * L + (tid - 2 * L)];
        idx[tid] = v;
    }
    __syncthreads();

    const float4* __restrict__ emb4 = (const float4*)emb;
    const int p    = tid >> 6;   // 4 parts split the l-range -> MLP + parallelism
    const int lane = tid & 63;   // float4 channel

    float4 q  = make_float4(0.f, 0.f, 0.f, 0.f);
    float4 sv = make_float4(0.f, 0.f, 0.f, 0.f);

    #pragma unroll 13
    for (int l = p; l < L; l += 4) {
        float4 e = emb4[(size_t)idx[l] * (D / 4) + lane];
        q.x += e.x; q.y += e.y; q.z += e.z; q.w += e.w;
    }
    // slot + value lists both accumulate into sv (indices 50..149)
    #pragma unroll 25
    for (int l = L + p; l < 3 * L; l += 4) {
        float4 e = emb4[(size_t)idx[l] * (D / 4) + lane];
        sv.x += e.x; sv.y += e.y; sv.z += e.z; sv.w += e.w;
    }

    redq [p][lane] = q;
    redsv[p][lane] = sv;
    __syncthreads();

    if (tid < 64) {
        float4 a = redq[0][tid], c = redq[1][tid], d = redq[2][tid], e = redq[3][tid];
        float4 s = make_float4(a.x + c.x + d.x + e.x, a.y + c.y + d.y + e.y,
                               a.z + c.z + d.z + e.z, a.w + c.w + d.w + e.w);
        g_tq[b * (D / 4) + tid] = s;
    } else if (tid < 128) {
        int ln = tid - 64;
        float4 a = redsv[0][ln], c = redsv[1][ln], d = redsv[2][ln], e = redsv[3][ln];
        float4 s = make_float4(a.x + c.x + d.x + e.x, a.y + c.y + d.y + e.y,
                               a.z + c.z + d.z + e.z, a.w + c.w + d.w + e.w);
        g_tsv[b * (D / 4) + ln] = s;
    }
}

__device__ __forceinline__ float fsigmoid(float x) {
    return 1.0f / (1.0f + __expf(-x));
}

// ---------------- Kernel 2: per-batch GEMV x2 (packed f32x2) + gate epilogue -
__global__ void __launch_bounds__(256) gemm_gate_kernel(
    const int*   __restrict__ slot_names,
    const float* __restrict__ emb,
    float*       __restrict__ out)
{
    __shared__ __align__(16) float4 tq_sm [BM2 * (D / 4)];  // 16 KB
    __shared__ __align__(16) float4 tsv_sm[BM2 * (D / 4)];  // 16 KB
    __shared__ int sidx[BM2 * 4];

    const int tid = threadIdx.x;
    const int b0  = blockIdx.x * BM2;

    for (int k = tid; k < BM2 * (D / 4); k += 256) {
        tq_sm [k] = g_tq [b0 * (D / 4) + k];
        tsv_sm[k] = g_tsv[b0 * (D / 4) + k];
    }
    if (tid < BM2 * 4) sidx[tid] = slot_names[b0 * 4 + tid];
    __syncthreads();

    const int i = tid;  // output channel owned by this thread
    float gq[BM2], gs[BM2];

    // ---- pass 1: g_q = w1 @ t_q ----
    {
        unsigned long long acc[BM2];
        #pragma unroll
        for (int b = 0; b < BM2; b++) acc[b] = 0ull;
        const float4* __restrict__ wv = (const float4*)g_w1p;
        for (int j4 = 0; j4 < D / 4; j4++) {
            float4 w = wv[j4 * D + i];                 // coalesced LDG.128
            unsigned long long w01, w23;
            PACK2(w01, w.x, w.y); PACK2(w23, w.z, w.w);
            #pragma unroll
            for (int b = 0; b < BM2; b++) {
                float4 t = tq_sm[b * (D / 4) + j4];    // broadcast LDS.128
                unsigned long long t01, t23;
                PACK2(t01, t.x, t.y); PACK2(t23, t.z, t.w);
                FMA2(acc[b], w01, t01);
                FMA2(acc[b], w23, t23);
            }
        }
        #pragma unroll
        for (int b = 0; b < BM2; b++) {
            float lo, hi; UNPACK2(lo, hi, acc[b]); gq[b] = lo + hi;
        }
    }

    // ---- pass 2: g_sv = w2 @ (t_s + t_v) ----
    {
        unsigned long long acc[BM2];
        #pragma unroll
        for (int b = 0; b < BM2; b++) acc[b] = 0ull;
        const float4* __restrict__ wv = (const float4*)g_w2p;
        for (int j4 = 0; j4 < D / 4; j4++) {
            float4 w = wv[j4 * D + i];
            unsigned long long w01, w23;
            PACK2(w01, w.x, w.y); PACK2(w23, w.z, w.w);
            #pragma unroll
            for (int b = 0; b < BM2; b++) {
                float4 t = tsv_sm[b * (D / 4) + j4];
                unsigned long long t01, t23;
                PACK2(t01, t.x, t.y); PACK2(t23, t.z, t.w);
                FMA2(acc[b], w01, t01);
                FMA2(acc[b], w23, t23);
            }
        }
        #pragma unroll
        for (int b = 0; b < BM2; b++) {
            float lo, hi; UNPACK2(lo, hi, acc[b]); gs[b] = lo + hi;
        }
    }

    // ---- epilogue: gates = c_s + sig(c_s*g_q) + sig(c_s*g_sv) ----
    for (int b = 0; b < BM2; b++) {
        const float q = gq[b];
        const float s = gs[b];
        const size_t ob = ((size_t)(b0 + b)) * 4;
        #pragma unroll
        for (int sl = 0; sl < 4; sl++) {
            int row = sidx[b * 4 + sl];
            float c = emb[(size_t)row * D + i];        // coalesced
            float o = c + fsigmoid(c * q) + fsigmoid(c * s);
            out[(ob + sl) * D + i] = o;                // coalesced
        }
    }
}

extern "C" void kernel_launch(void* const* d_in, const int* in_sizes, int n_in,
                              void* d_out, int out_size)
{
    const int*   acts_req   = (const int*)  d_in[0];
    const int*   acts_slot  = (const int*)  d_in[1];
    const int*   acts_val   = (const int*)  d_in[2];
    const int*   slot_names = (const int*)  d_in[3];
    const float* emb        = (const float*)d_in[4];
    const float* w1         = (const float*)d_in[5];
    const float* w2         = (const float*)d_in[6];
    float*       out        = (float*)d_out;

    repack_weights<<<D, D>>>(w1, w2);
    gather_kernel<<<BSZ, 256>>>(acts_req, acts_slot, acts_val, emb);
    gemm_gate_kernel<<<NBLK2, 256>>>(slot_names, emb, out);
}

// round 3
// speedup vs baseline: 1.5960x; 1.0454x over previous
#include <cuda_runtime.h>

#define D       256
#define L       50
#define BSZ     4096
#define BM2     16
#define NBLK2   (BSZ / BM2)

// Repacked transposed weights: float4 at [j4*D + i] = {w[i][4j4..4j4+3]}
__device__ float g_w1p[D * D];
__device__ float g_w2p[D * D];
// Scratch: t_q / t_sv per batch, 64 float4 channels per batch (8 MB total)
__device__ float4 g_tq [BSZ * (D / 4)];
__device__ float4 g_tsv[BSZ * (D / 4)];

#define PACK2(u, x, y)   asm("mov.b64 %0, {%1, %2};" : "=l"(u) : "f"(x), "f"(y))
#define UNPACK2(x, y, u) asm("mov.b64 {%0, %1}, %2;" : "=f"(x), "=f"(y) : "l"(u))
#define FMA2(acc, a, b)  asm("fma.rn.f32x2 %0, %1, %2, %0;" : "+l"(acc) : "l"(a), "l"(b))

__device__ __forceinline__ float fsigmoid(float x) {
    return 1.0f / (1.0f + __expf(-x));
}

// ------------- Kernel 1: ragged gather-sum (one block/batch) + weight repack -
__global__ void __launch_bounds__(256) gather_kernel(
    const int*   __restrict__ acts_req,
    const int*   __restrict__ acts_slot,
    const int*   __restrict__ acts_val,
    const float* __restrict__ w1,
    const float* __restrict__ w2,
    const float* __restrict__ emb)
{
    __shared__ int idx[3 * L + 2];
    __shared__ __align__(16) float4 redq [4][D / 4];   // 4 KB
    __shared__ __align__(16) float4 redsv[4][D / 4];   // 4 KB

    const int b   = blockIdx.x;
    const int tid = threadIdx.x;

    // Fold weight repack into the first 256 blocks (gemm runs after us in-stream)
    if (b < D) {
        int i = b;
        int j = tid;
        float v1 = w1[i * D + j];
        float v2 = w2[i * D + j];
        int o = ((j >> 2) * D + i) * 4 + (j & 3);
        g_w1p[o] = v1;
        g_w2p[o] = v2;
    }

    if (tid < 3 * L) {
        int v;
        if      (tid < L)     v = acts_req [b * L + tid];
        else if (tid < 2 * L) v = acts_slot[b * L + (tid - L)];
        else                  v = acts_val [b * L + (tid - 2 * L)];
        idx[tid] = v;
    }
    __syncthreads();

    const float4* __restrict__ emb4 = (const float4*)emb;
    const int p    = tid >> 6;   // 4 parts split the l-range
    const int lane = tid & 63;   // float4 channel

    float4 q0  = make_float4(0.f, 0.f, 0.f, 0.f);
    float4 q1  = make_float4(0.f, 0.f, 0.f, 0.f);
    float4 s0  = make_float4(0.f, 0.f, 0.f, 0.f);
    float4 s1  = make_float4(0.f, 0.f, 0.f, 0.f);

    // request list: l = p + 4k, k in [0,13) — fixed trip count, predicated,
    // dual accumulators -> ptxas can front-batch the independent LDGs.
    #pragma unroll
    for (int k = 0; k < 13; k++) {
        int l = p + 4 * k;
        if (l < L) {
            float4 e = emb4[(size_t)idx[l] * (D / 4) + lane];
            if (k & 1) { q1.x += e.x; q1.y += e.y; q1.z += e.z; q1.w += e.w; }
            else       { q0.x += e.x; q0.y += e.y; q0.z += e.z; q0.w += e.w; }
        }
    }
    // slot + value lists both accumulate into sv: l in [50,150)
    #pragma unroll
    for (int k = 0; k < 25; k++) {
        int l = L + p + 4 * k;
        if (l < 3 * L) {
            float4 e = emb4[(size_t)idx[l] * (D / 4) + lane];
            if (k & 1) { s1.x += e.x; s1.y += e.y; s1.z += e.z; s1.w += e.w; }
            else       { s0.x += e.x; s0.y += e.y; s0.z += e.z; s0.w += e.w; }
        }
    }

    redq [p][lane] = make_float4(q0.x + q1.x, q0.y + q1.y, q0.z + q1.z, q0.w + q1.w);
    redsv[p][lane] = make_float4(s0.x + s1.x, s0.y + s1.y, s0.z + s1.z, s0.w + s1.w);
    __syncthreads();

    if (tid < 64) {
        float4 a = redq[0][tid], c = redq[1][tid], d = redq[2][tid], e = redq[3][tid];
        g_tq[b * (D / 4) + tid] =
            make_float4(a.x + c.x + d.x + e.x, a.y + c.y + d.y + e.y,
                        a.z + c.z + d.z + e.z, a.w + c.w + d.w + e.w);
    } else if (tid < 128) {
        int ln = tid - 64;
        float4 a = redsv[0][ln], c = redsv[1][ln], d = redsv[2][ln], e = redsv[3][ln];
        g_tsv[b * (D / 4) + ln] =
            make_float4(a.x + c.x + d.x + e.x, a.y + c.y + d.y + e.y,
                        a.z + c.z + d.z + e.z, a.w + c.w + d.w + e.w);
    }
}

// ------------- Kernel 2: per-batch GEMV x2 (packed f32x2) + gate epilogue ----
__global__ void __launch_bounds__(256) gemm_gate_kernel(
    const int*   __restrict__ slot_names,
    const float* __restrict__ emb,
    float*       __restrict__ out)
{
    __shared__ __align__(16) float4 tq_sm [BM2 * (D / 4)];  // 16 KB
    __shared__ __align__(16) float4 tsv_sm[BM2 * (D / 4)];  // 16 KB
    __shared__ int sidx[BM2 * 4];

    const int tid = threadIdx.x;
    const int b0  = blockIdx.x * BM2;

    for (int k = tid; k < BM2 * (D / 4); k += 256) {
        tq_sm [k] = g_tq [b0 * (D / 4) + k];
        tsv_sm[k] = g_tsv[b0 * (D / 4) + k];
    }
    if (tid < BM2 * 4) sidx[tid] = slot_names[b0 * 4 + tid];
    __syncthreads();

    const int i = tid;  // output channel owned by this thread
    float gq[BM2], gs[BM2];

    // ---- pass 1: g_q = w1 @ t_q ----
    {
        unsigned long long acc[BM2];
        #pragma unroll
        for (int b = 0; b < BM2; b++) acc[b] = 0ull;
        const float4* __restrict__ wv = (const float4*)g_w1p;
        for (int j4 = 0; j4 < D / 4; j4++) {
            float4 w = wv[j4 * D + i];                 // coalesced LDG.128
            unsigned long long w01, w23;
            PACK2(w01, w.x, w.y); PACK2(w23, w.z, w.w);
            #pragma unroll
            for (int b = 0; b < BM2; b++) {
                float4 t = tq_sm[b * (D / 4) + j4];    // broadcast LDS.128
                unsigned long long t01, t23;
                PACK2(t01, t.x, t.y); PACK2(t23, t.z, t.w);
                FMA2(acc[b], w01, t01);
                FMA2(acc[b], w23, t23);
            }
        }
        #pragma unroll
        for (int b = 0; b < BM2; b++) {
            float lo, hi; UNPACK2(lo, hi, acc[b]); gq[b] = lo + hi;
        }
    }

    // ---- pass 2: g_sv = w2 @ (t_s + t_v) ----
    {
        unsigned long long acc[BM2];
        #pragma unroll
        for (int b = 0; b < BM2; b++) acc[b] = 0ull;
        const float4* __restrict__ wv = (const float4*)g_w2p;
        for (int j4 = 0; j4 < D / 4; j4++) {
            float4 w = wv[j4 * D + i];
            unsigned long long w01, w23;
            PACK2(w01, w.x, w.y); PACK2(w23, w.z, w.w);
            #pragma unroll
            for (int b = 0; b < BM2; b++) {
                float4 t = tsv_sm[b * (D / 4) + j4];
                unsigned long long t01, t23;
                PACK2(t01, t.x, t.y); PACK2(t23, t.z, t.w);
                FMA2(acc[b], w01, t01);
                FMA2(acc[b], w23, t23);
            }
        }
        #pragma unroll
        for (int b = 0; b < BM2; b++) {
            float lo, hi; UNPACK2(lo, hi, acc[b]); gs[b] = lo + hi;
        }
    }

    // ---- epilogue: gates = c_s + sig(c_s*g_q) + sig(c_s*g_sv) ----
    for (int b = 0; b < BM2; b++) {
        const float q = gq[b];
        const float s = gs[b];
        const size_t ob = ((size_t)(b0 + b)) * 4;
        #pragma unroll
        for (int sl = 0; sl < 4; sl++) {
            int row = sidx[b * 4 + sl];
            float c = emb[(size_t)row * D + i];        // coalesced
            float o = c + fsigmoid(c * q) + fsigmoid(c * s);
            out[(ob + sl) * D + i] = o;                // coalesced
        }
    }
}

extern "C" void kernel_launch(void* const* d_in, const int* in_sizes, int n_in,
                              void* d_out, int out_size)
{
    const int*   acts_req   = (const int*)  d_in[0];
    const int*   acts_slot  = (const int*)  d_in[1];
    const int*   acts_val   = (const int*)  d_in[2];
    const int*   slot_names = (const int*)  d_in[3];
    const float* emb        = (const float*)d_in[4];
    const float* w1         = (const float*)d_in[5];
    const float* w2         = (const float*)d_in[6];
    float*       out        = (float*)d_out;

    gather_kernel<<<BSZ, 256>>>(acts_req, acts_slot, acts_val, w1, w2, emb);
    gemm_gate_kernel<<<NBLK2, 256>>>(slot_names, emb, out);
}

// round 4
// speedup vs baseline: 2.1254x; 1.3317x over previous
#include <cuda_runtime.h>

#define D       256
#define L       50
#define BSZ     4096
#define JP      4                    // K-dim split factor
#define JW      (D / 4 / JP)         // 16 float4-steps per part
#define BMG     16                   // batches per partial-gemm block
#define BMR     8                    // batches per reduce block

// Repacked transposed weights: float4 at [j4*D + i] = {w[i][4j4..4j4+3]}
__device__ float g_w1p[D * D];
__device__ float g_w2p[D * D];
// Gather outputs: 64 float4 channels per batch (8 MB total)
__device__ float4 g_tq [BSZ * (D / 4)];
__device__ float4 g_tsv[BSZ * (D / 4)];
// Partial GEMV results [part][batch][channel] (16 MB each)
__device__ float g_pq[JP * BSZ * D];
__device__ float g_ps[JP * BSZ * D];

#define FMA2(acc, a, b)  asm("fma.rn.f32x2 %0, %1, %2, %0;" : "+l"(acc) : "l"(a), "l"(b))
#define UNPACK2(x, y, u) asm("mov.b64 {%0, %1}, %2;" : "=f"(x), "=f"(y) : "l"(u))

__device__ __forceinline__ float fsigmoid(float x) {
    return 1.0f / (1.0f + __expf(-x));
}

// ------------- Kernel 1: ragged gather-sum (one block/batch) + weight repack -
__global__ void __launch_bounds__(256) gather_kernel(
    const int*   __restrict__ acts_req,
    const int*   __restrict__ acts_slot,
    const int*   __restrict__ acts_val,
    const float* __restrict__ w1,
    const float* __restrict__ w2,
    const float* __restrict__ emb)
{
    __shared__ int idx[3 * L + 2];
    __shared__ __align__(16) float4 redq [4][D / 4];
    __shared__ __align__(16) float4 redsv[4][D / 4];

    const int b   = blockIdx.x;
    const int tid = threadIdx.x;

    // Fold weight repack into the first 256 blocks (gemm launches after us)
    if (b < D) {
        int i = b, j = tid;
        float v1 = w1[i * D + j];
        float v2 = w2[i * D + j];
        int o = ((j >> 2) * D + i) * 4 + (j & 3);
        g_w1p[o] = v1;
        g_w2p[o] = v2;
    }

    if (tid < 3 * L) {
        int v;
        if      (tid < L)     v = acts_req [b * L + tid];
        else if (tid < 2 * L) v = acts_slot[b * L + (tid - L)];
        else                  v = acts_val [b * L + (tid - 2 * L)];
        idx[tid] = v;
    }
    __syncthreads();

    const float4* __restrict__ emb4 = (const float4*)emb;
    const int p    = tid >> 6;
    const int lane = tid & 63;

    float4 q0 = make_float4(0.f,0.f,0.f,0.f), q1 = q0, s0 = q0, s1 = q0;

    #pragma unroll
    for (int k = 0; k < 13; k++) {
        int l = p + 4 * k;
        if (l < L) {
            float4 e = emb4[(size_t)idx[l] * (D / 4) + lane];
            if (k & 1) { q1.x += e.x; q1.y += e.y; q1.z += e.z; q1.w += e.w; }
            else       { q0.x += e.x; q0.y += e.y; q0.z += e.z; q0.w += e.w; }
        }
    }
    #pragma unroll
    for (int k = 0; k < 25; k++) {
        int l = L + p + 4 * k;
        if (l < 3 * L) {
            float4 e = emb4[(size_t)idx[l] * (D / 4) + lane];
            if (k & 1) { s1.x += e.x; s1.y += e.y; s1.z += e.z; s1.w += e.w; }
            else       { s0.x += e.x; s0.y += e.y; s0.z += e.z; s0.w += e.w; }
        }
    }

    redq [p][lane] = make_float4(q0.x+q1.x, q0.y+q1.y, q0.z+q1.z, q0.w+q1.w);
    redsv[p][lane] = make_float4(s0.x+s1.x, s0.y+s1.y, s0.z+s1.z, s0.w+s1.w);
    __syncthreads();

    if (tid < 64) {
        float4 a = redq[0][tid], c = redq[1][tid], d = redq[2][tid], e = redq[3][tid];
        g_tq[b * (D / 4) + tid] =
            make_float4(a.x+c.x+d.x+e.x, a.y+c.y+d.y+e.y, a.z+c.z+d.z+e.z, a.w+c.w+d.w+e.w);
    } else if (tid < 128) {
        int ln = tid - 64;
        float4 a = redsv[0][ln], c = redsv[1][ln], d = redsv[2][ln], e = redsv[3][ln];
        g_tsv[b * (D / 4) + ln] =
            make_float4(a.x+c.x+d.x+e.x, a.y+c.y+d.y+e.y, a.z+c.z+d.z+e.z, a.w+c.w+d.w+e.w);
    }
}

// ------------- Kernel 2a: K-split partial GEMV (f32x2), 1024 blocks ---------
__global__ void __launch_bounds__(256) partial_gemm(void)
{
    __shared__ __align__(16) ulonglong2 tq_sm [BMG * JW];  // 4 KB
    __shared__ __align__(16) ulonglong2 tsv_sm[BMG * JW];  // 4 KB

    const int tid = threadIdx.x;
    const int jp  = blockIdx.x & (JP - 1);       // K part
    const int bg  = blockIdx.x >> 2;             // batch group
    const int b0  = bg * BMG;
    const int j0  = jp * JW;                     // first float4-step

    // stage t chunks (exactly one load per thread: 16*16 = 256)
    {
        int b = tid >> 4, jl = tid & (JW - 1);
        const ulonglong2* tq2  = (const ulonglong2*)g_tq;
        const ulonglong2* tsv2 = (const ulonglong2*)g_tsv;
        tq_sm [tid] = tq2 [(b0 + b) * (D / 4) + j0 + jl];
        tsv_sm[tid] = tsv2[(b0 + b) * (D / 4) + j0 + jl];
    }
    __syncthreads();

    const int i = tid;   // output channel

    // ---- pass 1: partial g_q ----
    {
        unsigned long long acc[BMG];
        #pragma unroll
        for (int b = 0; b < BMG; b++) acc[b] = 0ull;
        const ulonglong2* __restrict__ wv = (const ulonglong2*)g_w1p;
        #pragma unroll
        for (int jl = 0; jl < JW; jl++) {
            ulonglong2 w = wv[(j0 + jl) * D + i];          // coalesced LDG.128
            #pragma unroll
            for (int b = 0; b < BMG; b++) {
                ulonglong2 t = tq_sm[(b << 4) + jl];       // broadcast LDS.128
                FMA2(acc[b], w.x, t.x);
                FMA2(acc[b], w.y, t.y);
            }
        }
        #pragma unroll
        for (int b = 0; b < BMG; b++) {
            float lo, hi; UNPACK2(lo, hi, acc[b]);
            g_pq[((size_t)jp * BSZ + b0 + b) * D + i] = lo + hi;
        }
    }

    // ---- pass 2: partial g_sv ----
    {
        unsigned long long acc[BMG];
        #pragma unroll
        for (int b = 0; b < BMG; b++) acc[b] = 0ull;
        const ulonglong2* __restrict__ wv = (const ulonglong2*)g_w2p;
        #pragma unroll
        for (int jl = 0; jl < JW; jl++) {
            ulonglong2 w = wv[(j0 + jl) * D + i];
            #pragma unroll
            for (int b = 0; b < BMG; b++) {
                ulonglong2 t = tsv_sm[(b << 4) + jl];
                FMA2(acc[b], w.x, t.x);
                FMA2(acc[b], w.y, t.y);
            }
        }
        #pragma unroll
        for (int b = 0; b < BMG; b++) {
            float lo, hi; UNPACK2(lo, hi, acc[b]);
            g_ps[((size_t)jp * BSZ + b0 + b) * D + i] = lo + hi;
        }
    }
}

// ------------- Kernel 2b: reduce partials + gate epilogue, 512 blocks -------
__global__ void __launch_bounds__(256) reduce_gate(
    const int*   __restrict__ slot_names,
    const float* __restrict__ emb,
    float*       __restrict__ out)
{
    __shared__ int sidx[BMR * 4];

    const int tid = threadIdx.x;
    const int b0  = blockIdx.x * BMR;

    if (tid < BMR * 4) sidx[tid] = slot_names[b0 * 4 + tid];
    __syncthreads();

    const int i = tid;
    #pragma unroll
    for (int b = 0; b < BMR; b++) {
        const size_t base = (size_t)(b0 + b) * D + i;
        float gq = 0.f, gs = 0.f;
        #pragma unroll
        for (int p = 0; p < JP; p++) {
            gq += g_pq[(size_t)p * BSZ * D + base];
            gs += g_ps[(size_t)p * BSZ * D + base];
        }
        const size_t ob = ((size_t)(b0 + b)) * 4;
        #pragma unroll
        for (int sl = 0; sl < 4; sl++) {
            int row = sidx[b * 4 + sl];
            float c = emb[(size_t)row * D + i];
            out[(ob + sl) * D + i] = c + fsigmoid(c * gq) + fsigmoid(c * gs);
        }
    }
}

extern "C" void kernel_launch(void* const* d_in, const int* in_sizes, int n_in,
                              void* d_out, int out_size)
{
    const int*   acts_req   = (const int*)  d_in[0];
    const int*   acts_slot  = (const int*)  d_in[1];
    const int*   acts_val   = (const int*)  d_in[2];
    const int*   slot_names = (const int*)  d_in[3];
    const float* emb        = (const float*)d_in[4];
    const float* w1         = (const float*)d_in[5];
    const float* w2         = (const float*)d_in[6];
    float*       out        = (float*)d_out;

    gather_kernel<<<BSZ, 256>>>(acts_req, acts_slot, acts_val, w1, w2, emb);
    partial_gemm<<<(BSZ / BMG) * JP, 256>>>();
    reduce_gate<<<BSZ / BMR, 256>>>(slot_names, emb, out);
}